// round 2
// baseline (speedup 1.0000x reference)
#include <cuda_runtime.h>

#define NBINS 256

// Scratch (no allocs allowed): histograms for 6 channels (3 src + 3 tgt) and the
// per-channel pixel-value remap table.
__device__ int   g_hist[6][NBINS];
__device__ float g_pxmap[3][NBINS];

// colorspace: clip(-1 + k/127, -1, 1), replicated in f32 like the reference.
__device__ __forceinline__ float csf(int k) {
    float v = -1.0f + (float)k / 127.0f;
    return fminf(fmaxf(v, -1.0f), 1.0f);
}

__global__ void zero_hist_kernel() {
    int i = blockIdx.x * blockDim.x + threadIdx.x;
    if (i < 6 * NBINS) ((int*)g_hist)[i] = 0;
}

// One pass over both images; shared-memory privatized histograms.
// Element e = 4*i + lane has channel e % 3; (4*i) % 3 == i % 3.
__global__ void hist_kernel(const float4* __restrict__ src4,
                            const float4* __restrict__ tgt4, int n4) {
    __shared__ int sh[6 * NBINS];
    for (int i = threadIdx.x; i < 6 * NBINS; i += blockDim.x) sh[i] = 0;
    __syncthreads();

    int stride = gridDim.x * blockDim.x;
    for (int i = blockIdx.x * blockDim.x + threadIdx.x; i < n4; i += stride) {
        float4 a = src4[i];
        float4 b = tgt4[i];
        float va[4] = {a.x, a.y, a.z, a.w};
        float vb[4] = {b.x, b.y, b.z, b.w};
        int c = i % 3;
#pragma unroll
        for (int l = 0; l < 4; l++) {
            float v = fminf(fmaxf(va[l], -1.0f), 1.0f);
            int bin = (int)((v + 1.0f) * 128.0f);
            bin = min(max(bin, 0), NBINS - 1);
            atomicAdd(&sh[c * NBINS + bin], 1);

            v = fminf(fmaxf(vb[l], -1.0f), 1.0f);
            bin = (int)((v + 1.0f) * 128.0f);
            bin = min(max(bin, 0), NBINS - 1);
            atomicAdd(&sh[(3 + c) * NBINS + bin], 1);

            c++; if (c == 3) c = 0;
        }
    }
    __syncthreads();
    for (int i = threadIdx.x; i < 6 * NBINS; i += blockDim.x) {
        int v = sh[i];
        if (v) atomicAdd(&((int*)g_hist)[i], v);
    }
}

// Single block, 256 threads: cumsum -> equalized cdf for 6 channels, then
// pxmap[ch][k] = interpolate(dx=cdftgt, dy=cs, x=cdfsrc[k]) with the
// reference's nearest-index (first-occurrence tie) + boundary semantics.
__global__ void pxmap_kernel() {
    __shared__ float eq[6][NBINS];
    __shared__ int   s_h[NBINS];
    int t = threadIdx.x;  // 0..255

    for (int a = 0; a < 6; a++) {
        s_h[t] = g_hist[a][t];
        __syncthreads();
        int c = 0;
        for (int j = 0; j <= t; j++) c += s_h[j];   // inclusive scan (tiny)
        int cdf0 = s_h[0];                          // min of nondecreasing cdf
        eq[a][t] = ((float)(c - cdf0) * 2.0f) / 1048575.0f - 1.0f;
        __syncthreads();
    }

    for (int ch = 0; ch < 3; ch++) {
        float x = eq[ch][t];            // cdfsrc value
        const float* dx = eq[3 + ch];   // cdftgt
        float best = fabsf(dx[0] - x);
        int ind1 = 0;
        for (int j = 1; j < NBINS; j++) {
            float d = fabsf(dx[j] - x);
            if (d < best) { best = d; ind1 = j; }   // strict < keeps first occurrence
        }
        int ind0 = max(ind1 - 1, 0);
        float x0 = dx[ind0], x1 = dx[ind1];
        float y0 = csf(ind0), y1 = csf(ind1);
        float denom = x1 - x0;
        float safe = (denom == 0.0f) ? 1.0f : denom;
        float interp = y0 + (y1 - y0) * (x - x0) / safe;
        float res = (x <= dx[0]) ? csf(0)
                  : ((x >= dx[NBINS - 1]) ? csf(NBINS - 1) : interp);
        g_pxmap[ch][t] = res;
    }
}

// Per-pixel map: analytic nearest index into the uniform cs grid
// (ties to lower index to match argmin-first-occurrence), then the
// reference's segment [ind1-1, ind1] linear formula with boundary overrides.
__global__ void map_kernel(const float4* __restrict__ src4,
                           float4* __restrict__ out4, int n4) {
    __shared__ float px[3][NBINS];
    for (int i = threadIdx.x; i < 3 * NBINS; i += blockDim.x)
        ((float*)px)[i] = ((const float*)g_pxmap)[i];
    __syncthreads();

    int stride = gridDim.x * blockDim.x;
    for (int i = blockIdx.x * blockDim.x + threadIdx.x; i < n4; i += stride) {
        float4 a = src4[i];
        float v[4] = {a.x, a.y, a.z, a.w};
        float r[4];
        int c = i % 3;
#pragma unroll
        for (int l = 0; l < 4; l++) {
            float x = v[l];
            const float* p = px[c];
            float y;
            if (x <= -1.0f) {
                y = p[0];
            } else if (x >= 1.0f) {
                y = p[NBINS - 1];
            } else {
                float tt = (x + 1.0f) * 127.0f;
                int i1 = (int)ceilf(tt - 0.5f);      // ties -> lower index
                i1 = min(max(i1, 0), NBINS - 1);
                int i0 = max(i1 - 1, 0);
                float x0 = csf(i0), x1 = csf(i1);
                float y0 = p[i0],  y1 = p[i1];
                float denom = x1 - x0;
                float safe = (denom == 0.0f) ? 1.0f : denom;
                y = y0 + (y1 - y0) * (x - x0) / safe;
            }
            r[l] = y;
            c++; if (c == 3) c = 0;
        }
        out4[i] = make_float4(r[0], r[1], r[2], r[3]);
    }
}

extern "C" void kernel_launch(void* const* d_in, const int* in_sizes, int n_in,
                              void* d_out, int out_size) {
    const float* src = (const float*)d_in[0];
    const float* tgt = (const float*)d_in[1];
    float* out = (float*)d_out;

    int n  = in_sizes[0];        // 1024*1024*3 = 3145728
    int n4 = n / 4;              // 786432 float4s (divisible)

    zero_hist_kernel<<<6, 256>>>();
    hist_kernel<<<1024, 256>>>((const float4*)src, (const float4*)tgt, n4);
    pxmap_kernel<<<1, 256>>>();
    map_kernel<<<1024, 256>>>((const float4*)src, (float4*)out, n4);
}

// round 3
// speedup vs baseline: 1.2901x; 1.2901x over previous
#include <cuda_runtime.h>

#define NBINS 256

// Scratch: histograms for 6 channels (3 src + 3 tgt) and per-channel
// per-bin linear map coefficients  y = A + B*x.
__device__ int    g_hist[6][NBINS];
__device__ float2 g_coef[3][NBINS];

// colorspace: clip(-1 + k/127, -1, 1), replicated in f32 like the reference.
__device__ __forceinline__ float csf(int k) {
    float v = -1.0f + (float)k / 127.0f;
    return fminf(fmaxf(v, -1.0f), 1.0f);
}

__global__ void zero_hist_kernel() {
    int i = blockIdx.x * blockDim.x + threadIdx.x;
    if (i < 6 * NBINS) ((int*)g_hist)[i] = 0;
}

// One pass over both images; shared-memory privatized histograms.
// Element e = 4*i + lane has channel e % 3; (4*i) % 3 == i % 3.
__global__ void hist_kernel(const float4* __restrict__ src4,
                            const float4* __restrict__ tgt4, int n4) {
    __shared__ int sh[6 * NBINS];
    for (int i = threadIdx.x; i < 6 * NBINS; i += blockDim.x) sh[i] = 0;
    __syncthreads();

    int stride = gridDim.x * blockDim.x;
    for (int i = blockIdx.x * blockDim.x + threadIdx.x; i < n4; i += stride) {
        float4 a = src4[i];
        float4 b = tgt4[i];
        float va[4] = {a.x, a.y, a.z, a.w};
        float vb[4] = {b.x, b.y, b.z, b.w};
        int c = i % 3;
#pragma unroll
        for (int l = 0; l < 4; l++) {
            float v = fminf(fmaxf(va[l], -1.0f), 1.0f);
            int bin = (int)((v + 1.0f) * 128.0f);
            bin = min(max(bin, 0), NBINS - 1);
            atomicAdd(&sh[c * NBINS + bin], 1);

            v = fminf(fmaxf(vb[l], -1.0f), 1.0f);
            bin = (int)((v + 1.0f) * 128.0f);
            bin = min(max(bin, 0), NBINS - 1);
            atomicAdd(&sh[(3 + c) * NBINS + bin], 1);

            c++; if (c == 3) c = 0;
        }
    }
    __syncthreads();
    for (int i = threadIdx.x; i < 6 * NBINS; i += blockDim.x) {
        int v = sh[i];
        if (v) atomicAdd(&((int*)g_hist)[i], v);
    }
}

// Single block, 256 threads.
// 1) shfl-based inclusive scan -> equalized cdf for 6 channels
// 2) pxmap[ch][k] = interpolate(cdftgt, cs, cdfsrc[k]) (reference semantics:
//    first-occurrence argmin, segment [ind1-1, ind1], boundary overrides)
// 3) per-bin linear coefficients (A, B) for the final per-pixel map.
__global__ void pxmap_kernel() {
    __shared__ float eq[6][NBINS];
    __shared__ float px[3][NBINS];
    __shared__ int   wsum[8];
    int t = threadIdx.x;       // 0..255
    int lane = t & 31, wid = t >> 5;

    for (int a = 0; a < 6; a++) {
        int v = g_hist[a][t];
        int cdf0 = g_hist[a][0];
        // intra-warp inclusive scan
#pragma unroll
        for (int d = 1; d < 32; d <<= 1) {
            int u = __shfl_up_sync(0xffffffffu, v, d);
            if (lane >= d) v += u;
        }
        if (lane == 31) wsum[wid] = v;
        __syncthreads();
        if (wid == 0 && lane < 8) {
            int s = wsum[lane];
#pragma unroll
            for (int d = 1; d < 8; d <<= 1) {
                int u = __shfl_up_sync(0xffu, s, d);
                if (lane >= d) s += u;
            }
            wsum[lane] = s;
        }
        __syncthreads();
        int cdf = v + ((wid > 0) ? wsum[wid - 1] : 0);
        eq[a][t] = (float)(cdf - cdf0) * 2.0f / 1048575.0f - 1.0f;
        __syncthreads();   // wsum reused next channel
    }

    // stage-1 interpolate: brute-force argmin like the reference
    for (int ch = 0; ch < 3; ch++) {
        float x = eq[ch][t];            // cdfsrc value
        const float* dx = eq[3 + ch];   // cdftgt
        float best = fabsf(dx[0] - x);
        int ind1 = 0;
        for (int j = 1; j < NBINS; j++) {
            float d = fabsf(dx[j] - x);
            if (d < best) { best = d; ind1 = j; }   // strict < = first occurrence
        }
        int ind0 = max(ind1 - 1, 0);
        float x0 = dx[ind0], x1 = dx[ind1];
        float y0 = csf(ind0), y1 = csf(ind1);
        float denom = x1 - x0;
        float safe = (denom == 0.0f) ? 1.0f : denom;
        float interp = y0 + (y1 - y0) * (x - x0) / safe;
        px[ch][t] = (x <= dx[0]) ? csf(0)
                  : ((x >= dx[NBINS - 1]) ? csf(NBINS - 1) : interp);
    }
    __syncthreads();

    // per-bin coefficients: for index i1 chosen by the map kernel,
    //   y = A[i1] + B[i1]*x
    // i1==0   -> y = px[0]        (covers x<=-1 boundary AND degenerate seg)
    // i1==255 -> y = px[255]      (only selected when x>=1 boundary)
    // else    -> segment [i1-1, i1] lerp on the uniform cs grid
    for (int ch = 0; ch < 3; ch++) {
        float A, B;
        if (t == 0)        { A = px[ch][0];   B = 0.0f; }
        else if (t == 255) { A = px[ch][255]; B = 0.0f; }
        else {
            float x0 = csf(t - 1), x1 = csf(t);
            float y0 = px[ch][t - 1], y1 = px[ch][t];
            float denom = x1 - x0;
            float safe = (denom == 0.0f) ? 1.0f : denom;
            float slope = (y1 - y0) / safe;
            A = y0 - slope * x0;
            B = slope;
        }
        g_coef[ch][t] = make_float2(A, B);
    }
}

// Per-pixel map: i1 = ceil((x+1)*127 - 0.5)  (ties -> lower index, matching
// argmin first-occurrence on the uniform grid), then y = A[i1] + B[i1]*x.
__global__ void map_kernel(const float4* __restrict__ src4,
                           float4* __restrict__ out4, int n4) {
    __shared__ float2 sc[3][NBINS];
    for (int i = threadIdx.x; i < 3 * NBINS; i += blockDim.x)
        ((float2*)sc)[i] = ((const float2*)g_coef)[i];
    __syncthreads();

    int stride = gridDim.x * blockDim.x;
    for (int i = blockIdx.x * blockDim.x + threadIdx.x; i < n4; i += stride) {
        float4 a = src4[i];
        float v[4] = {a.x, a.y, a.z, a.w};
        float r[4];
        int c = i % 3;
#pragma unroll
        for (int l = 0; l < 4; l++) {
            float x = v[l];
            float tt = fmaf(x, 127.0f, 126.5f);      // (x+1)*127 - 0.5
            int i1 = __float2int_ru(tt);             // ceil
            i1 = min(max(i1, 0), 254);
            if (x >= 1.0f) i1 = 255;                 // x >= dx[-1] override
            float2 ab = sc[c][i1];
            r[l] = fmaf(ab.y, x, ab.x);
            c++; if (c == 3) c = 0;
        }
        out4[i] = make_float4(r[0], r[1], r[2], r[3]);
    }
}

extern "C" void kernel_launch(void* const* d_in, const int* in_sizes, int n_in,
                              void* d_out, int out_size) {
    const float* src = (const float*)d_in[0];
    const float* tgt = (const float*)d_in[1];
    float* out = (float*)d_out;

    int n  = in_sizes[0];        // 1024*1024*3
    int n4 = n / 4;

    zero_hist_kernel<<<6, 256>>>();
    hist_kernel<<<1024, 256>>>((const float4*)src, (const float4*)tgt, n4);
    pxmap_kernel<<<1, 256>>>();
    map_kernel<<<1024, 256>>>((const float4*)src, (float4*)out, n4);
}

// round 5
// speedup vs baseline: 1.3883x; 1.0761x over previous
#include <cuda_runtime.h>

#define NBINS 256

// Scratch: histograms for 6 channels (3 src + 3 tgt) and per-channel
// per-bin linear map coefficients  y = A + B*x.
// g_hist is zero-initialized at module load; pxmap_kernel re-zeros it after
// consuming it, so every kernel_launch call sees zeros (graph-replay safe).
__device__ int    g_hist[6][NBINS];
__device__ float2 g_coef[3][NBINS];

// colorspace: clip(-1 + k/127, -1, 1), replicated in f32 like the reference.
__device__ __forceinline__ float csf(int k) {
    float v = -1.0f + (float)k / 127.0f;
    return fminf(fmaxf(v, -1.0f), 1.0f);
}

__device__ __forceinline__ int bin_of(float v) {
    v = fminf(fmaxf(v, -1.0f), 1.0f);
    int b = (int)((v + 1.0f) * 128.0f);
    return min(max(b, 0), NBINS - 1);
}

// One pass over both images; shared-memory privatized histograms.
// Element e = 4*i + lane has channel (i + lane) % 3.
// All loads for a thread's 3 iterations are issued up front (MLP=6) so DRAM
// latency overlaps the shared-atomic stream.
__global__ void hist_kernel(const float4* __restrict__ src4,
                            const float4* __restrict__ tgt4, int n4) {
    __shared__ int sh[6 * NBINS];
    for (int i = threadIdx.x; i < 6 * NBINS; i += blockDim.x) sh[i] = 0;
    __syncthreads();

    const int nthreads = gridDim.x * blockDim.x;
    const int g = blockIdx.x * blockDim.x + threadIdx.x;

    float4 a[3], b[3];
    int idx[3];
#pragma unroll
    for (int j = 0; j < 3; j++) {
        int i = g + j * nthreads;
        idx[j] = i;
        if (i < n4) { a[j] = src4[i]; b[j] = tgt4[i]; }
    }
#pragma unroll
    for (int j = 0; j < 3; j++) {
        int i = idx[j];
        if (i >= n4) break;
        float va[4] = {a[j].x, a[j].y, a[j].z, a[j].w};
        float vb[4] = {b[j].x, b[j].y, b[j].z, b[j].w};
        int c = i % 3;
#pragma unroll
        for (int l = 0; l < 4; l++) {
            atomicAdd(&sh[c * NBINS + bin_of(va[l])], 1);
            atomicAdd(&sh[(3 + c) * NBINS + bin_of(vb[l])], 1);
            c++; if (c == 3) c = 0;
        }
    }
    // tail safety for sizes beyond 3*nthreads*4 elements (not hit at 1024^2x3)
    for (int i = g + 3 * nthreads; i < n4; i += nthreads) {
        float4 aa = src4[i], bb = tgt4[i];
        float va[4] = {aa.x, aa.y, aa.z, aa.w};
        float vb[4] = {bb.x, bb.y, bb.z, bb.w};
        int c = i % 3;
#pragma unroll
        for (int l = 0; l < 4; l++) {
            atomicAdd(&sh[c * NBINS + bin_of(va[l])], 1);
            atomicAdd(&sh[(3 + c) * NBINS + bin_of(vb[l])], 1);
            c++; if (c == 3) c = 0;
        }
    }

    __syncthreads();
    for (int i = threadIdx.x; i < 6 * NBINS; i += blockDim.x) {
        int v = sh[i];
        if (v) atomicAdd(&((int*)g_hist)[i], v);
    }
}

// Single block, 256 threads.
// 1) shfl inclusive scan -> equalized cdf for 6 channels
// 2) pxmap[ch][k] = interpolate(cdftgt, cs, cdfsrc[k])  (reference semantics)
// 3) per-bin linear coefficients (A, B) for the final per-pixel map
// 4) re-zero g_hist for the next launch.
__global__ void pxmap_kernel() {
    __shared__ float eq[6][NBINS];
    __shared__ float px[3][NBINS];
    __shared__ int   wsum[8];
    int t = threadIdx.x;       // 0..255
    int lane = t & 31, wid = t >> 5;

    for (int a = 0; a < 6; a++) {
        int v = g_hist[a][t];
        int cdf0 = g_hist[a][0];
#pragma unroll
        for (int d = 1; d < 32; d <<= 1) {
            int u = __shfl_up_sync(0xffffffffu, v, d);
            if (lane >= d) v += u;
        }
        if (lane == 31) wsum[wid] = v;
        __syncthreads();
        if (wid == 0 && lane < 8) {
            int s = wsum[lane];
#pragma unroll
            for (int d = 1; d < 8; d <<= 1) {
                int u = __shfl_up_sync(0xffu, s, d);
                if (lane >= d) s += u;
            }
            wsum[lane] = s;
        }
        __syncthreads();
        int cdf = v + ((wid > 0) ? wsum[wid - 1] : 0);
        eq[a][t] = (float)(cdf - cdf0) * 2.0f / 1048575.0f - 1.0f;
        __syncthreads();   // wsum reused next channel
    }

    // re-zero g_hist for the next graph replay (hist already consumed)
    for (int a = 0; a < 6; a++) g_hist[a][t] = 0;

    // stage-1 interpolate: brute-force argmin like the reference
    for (int ch = 0; ch < 3; ch++) {
        float x = eq[ch][t];            // cdfsrc value
        const float* dx = eq[3 + ch];   // cdftgt
        float best = fabsf(dx[0] - x);
        int ind1 = 0;
        for (int j = 1; j < NBINS; j++) {
            float d = fabsf(dx[j] - x);
            if (d < best) { best = d; ind1 = j; }   // strict < = first occurrence
        }
        int ind0 = max(ind1 - 1, 0);
        float x0 = dx[ind0], x1 = dx[ind1];
        float y0 = csf(ind0), y1 = csf(ind1);
        float denom = x1 - x0;
        float safe = (denom == 0.0f) ? 1.0f : denom;
        float interp = y0 + (y1 - y0) * (x - x0) / safe;
        px[ch][t] = (x <= dx[0]) ? csf(0)
                  : ((x >= dx[NBINS - 1]) ? csf(NBINS - 1) : interp);
    }
    __syncthreads();

    // per-bin coefficients: y = A[i1] + B[i1]*x
    // i1==0   -> y = px[0]   (x<=-1 boundary / degenerate seg)
    // i1==255 -> y = px[255] (x>=1 boundary)
    for (int ch = 0; ch < 3; ch++) {
        float A, B;
        if (t == 0)        { A = px[ch][0];   B = 0.0f; }
        else if (t == 255) { A = px[ch][255]; B = 0.0f; }
        else {
            float x0 = csf(t - 1), x1 = csf(t);
            float y0 = px[ch][t - 1], y1 = px[ch][t];
            float denom = x1 - x0;
            float safe = (denom == 0.0f) ? 1.0f : denom;
            float slope = (y1 - y0) / safe;
            A = y0 - slope * x0;
            B = slope;
        }
        g_coef[ch][t] = make_float2(A, B);
    }
}

// Per-pixel map. Each thread handles 4 float4s whose loads are all issued
// before any compute (MLP=4) — grid sized to cover n4 exactly.
// i1 = ceil((x+1)*127 - 0.5) (ties -> lower index), y = A[i1] + B[i1]*x.
__global__ void map_kernel(const float4* __restrict__ src4,
                           float4* __restrict__ out4, int n4) {
    __shared__ float2 sc[3][NBINS];
    for (int i = threadIdx.x; i < 3 * NBINS; i += blockDim.x)
        ((float2*)sc)[i] = ((const float2*)g_coef)[i];
    __syncthreads();

    const int nthreads = gridDim.x * blockDim.x;
    const int g = blockIdx.x * blockDim.x + threadIdx.x;

    float4 a[4];
    int idx[4];
#pragma unroll
    for (int j = 0; j < 4; j++) {
        int i = g + j * nthreads;
        idx[j] = i;
        if (i < n4) a[j] = src4[i];
    }

#pragma unroll
    for (int j = 0; j < 4; j++) {
        int i = idx[j];
        if (i >= n4) continue;
        float v[4] = {a[j].x, a[j].y, a[j].z, a[j].w};
        float r[4];
        int c = i % 3;
#pragma unroll
        for (int l = 0; l < 4; l++) {
            float x = v[l];
            float tt = fmaf(x, 127.0f, 126.5f);      // (x+1)*127 - 0.5
            int i1 = __float2int_ru(tt);             // ceil
            i1 = min(max(i1, 0), 254);
            if (x >= 1.0f) i1 = 255;                 // x >= dx[-1] override
            float2 ab = sc[c][i1];
            r[l] = fmaf(ab.y, x, ab.x);
            c++; if (c == 3) c = 0;
        }
        out4[i] = make_float4(r[0], r[1], r[2], r[3]);
    }
}

extern "C" void kernel_launch(void* const* d_in, const int* in_sizes, int n_in,
                              void* d_out, int out_size) {
    const float* src = (const float*)d_in[0];
    const float* tgt = (const float*)d_in[1];
    float* out = (float*)d_out;

    int n  = in_sizes[0];        // 1024*1024*3
    int n4 = n / 4;              // 786432

    // hist: 1024 blocks x 256 thr x 3 float4-pairs = exact cover
    hist_kernel<<<1024, 256>>>((const float4*)src, (const float4*)tgt, n4);
    pxmap_kernel<<<1, 256>>>();
    // map: 768 blocks x 256 thr x 4 float4 = exact cover
    int nthreads = 768 * 256;
    (void)nthreads;
    map_kernel<<<768, 256>>>((const float4*)src, (float4*)out, n4);
}